// round 2
// baseline (speedup 1.0000x reference)
#include <cuda_runtime.h>
#include <cstdint>

#define D   128
#define NN  512
#define BB  4
#define RPB 8   // rows per block in row_kernel / expand_kernel

// Scratch (device globals — no allocation allowed)
__device__ float g_v1[D];
__device__ float g_base[BB * D];
__device__ float g_r[BB * NN * 4];   // per row: li0, li1, lj0, lj1

// ---------------------------------------------------------------------------
// Kernel S: fold W1 / embeddings / time-embedding into v1 and base[b].
// h[b,i] = relu(p * v1 + base[b]) reproduces relu(x @ W1 + b1) exactly.
// One block, 128 threads (thread = output dim d).
// ---------------------------------------------------------------------------
__global__ void setup_kernel(const int* __restrict__ t,
                             const float* __restrict__ TE,
                             const float* __restrict__ nc,
                             const float* __restrict__ EE,
                             const float* __restrict__ W1,
                             const float* __restrict__ b1)
{
    __shared__ float s_e0[D], s_e1[D], s_nc[D], s_te[BB][D];
    int tid = threadIdx.x;
    s_e0[tid] = EE[tid];
    s_e1[tid] = EE[D + tid];
    s_nc[tid] = nc[tid];
#pragma unroll
    for (int b = 0; b < BB; b++) s_te[b][tid] = TE[(size_t)t[b] * D + tid];
    __syncthreads();

    float v1 = 0.f, c0 = 0.f, c1 = 0.f;
    float te0 = 0.f, te1 = 0.f, te2 = 0.f, te3 = 0.f;
#pragma unroll 8
    for (int f = 0; f < D; f++) {
        float wA = W1[f * D + tid];              // rows [0,128): H_noisy
        float wB = W1[(D + f) * D + tid];        // rows [128,256): H_prev
        float wC = W1[(2 * D + f) * D + tid];    // rows [256,384): t_emb
        v1  = fmaf(s_e1[f] - s_e0[f], wA, v1);
        c0  = fmaf(s_e0[f],  wA, c0);
        c1  = fmaf(s_nc[f],  wB, c1);
        te0 = fmaf(s_te[0][f], wC, te0);
        te1 = fmaf(s_te[1][f], wC, te1);
        te2 = fmaf(s_te[2][f], wC, te2);
        te3 = fmaf(s_te[3][f], wC, te3);
    }
    g_v1[tid] = v1;
    float cb = c0 + c1 + b1[tid];
    g_base[0 * D + tid] = cb + te0;
    g_base[1 * D + tid] = cb + te1;
    g_base[2 * D + tid] = cb + te2;
    g_base[3 * D + tid] = cb + te3;
}

// ---------------------------------------------------------------------------
// Kernel B: per row i — p = mean(adj[b,i,:]); h = relu(p*v1 + base[b]);
// Hf = relu(h @ W2 + b2); (li, lj) = Hf @ Wc halves. Stores 4 floats/row.
// Grid: 256 blocks (64 per batch, 8 rows each), 256 threads.
// Dynamic smem: W2 (64KB) + h (4KB) + Hf (4KB) + Wc (2KB) + p (32B)
// ---------------------------------------------------------------------------
#define SMEM_B_FLOATS (16384 + 1024 + 1024 + 512 + 8)

__global__ void row_kernel(const int* __restrict__ adj,
                           const float* __restrict__ W2,
                           const float* __restrict__ b2,
                           const float* __restrict__ Wc)
{
    extern __shared__ float smem[];
    float* W2s = smem;                       // [d*128 + e]
    float* h_s = smem + 16384;               // [d*8 + r]
    float* Hfs = smem + 16384 + 1024;        // [r*128 + e]
    float* Wcs = smem + 16384 + 2048;        // [e*4 + c]  (li0,li1,lj0,lj1 weights)
    float* p_s = smem + 16384 + 2048 + 512;  // [8]

    const int tid  = threadIdx.x;
    const int b    = blockIdx.x >> 6;
    const int i0   = (blockIdx.x & 63) * RPB;
    const int grow0 = b * NN + i0;

    const int e    = tid & 127;
    const int g    = tid >> 7;       // 0/1: which 4-row group
    const int warp = tid >> 5;       // 0..7
    const int lane = tid & 31;

    // Load W2 into shared (coalesced float4 copy)
    {
        const float4* W2_4 = (const float4*)W2;
        float4* W2s_4 = (float4*)W2s;
#pragma unroll
        for (int k = 0; k < 16; k++) W2s_4[tid + k * 256] = W2_4[tid + k * 256];
    }

    // Per-thread constants for element e
    const float v1e   = g_v1[e];
    const float basee = g_base[b * D + e];
    const float b2e   = b2[e];
    if (g == 0) {
        float4 wc = make_float4(Wc[e * 2 + 0], Wc[e * 2 + 1],
                                Wc[(D + e) * 2 + 0], Wc[(D + e) * 2 + 1]);
        *(float4*)(Wcs + e * 4) = wc;
    }

    // p: warp w reduces row w (512 ints = 128 int4)
    {
        const int4* a4 = (const int4*)adj + (size_t)grow0 * (NN / 4);
        int s = 0;
#pragma unroll
        for (int k = 0; k < 4; k++) {
            int4 v = a4[warp * 128 + k * 32 + lane];
            s += v.x + v.y + v.z + v.w;
        }
#pragma unroll
        for (int o = 16; o; o >>= 1) s += __shfl_xor_sync(0xffffffffu, s, o);
        if (lane == 0) p_s[warp] = (float)s * (1.0f / 512.0f);
    }
    __syncthreads();

    // h for this thread's 4 rows at element e
    {
        float4 pr = *(const float4*)(p_s + 4 * g);
        float h0 = fmaxf(fmaf(pr.x, v1e, basee), 0.f);
        float h1 = fmaxf(fmaf(pr.y, v1e, basee), 0.f);
        float h2 = fmaxf(fmaf(pr.z, v1e, basee), 0.f);
        float h3 = fmaxf(fmaf(pr.w, v1e, basee), 0.f);
        *(float4*)(h_s + e * 8 + 4 * g) = make_float4(h0, h1, h2, h3);
    }
    __syncthreads();

    // Matvec: Hf[r][e] = relu(sum_d h[r][d] * W2[d][e] + b2[e]), 4 rows via f32x2
    unsigned long long acc0, acc1;
    {
        unsigned int ub = __float_as_uint(b2e);
        asm("mov.b64 %0, {%1, %1};" : "=l"(acc0) : "r"(ub));
        acc1 = acc0;
    }
#pragma unroll 8
    for (int d = 0; d < D; d++) {
        float w = W2s[d * D + e];
        ulonglong2 hh = *(const ulonglong2*)(h_s + d * 8 + 4 * g);
        unsigned long long w2;
        asm("mov.b64 %0, {%1, %1};" : "=l"(w2) : "r"(__float_as_uint(w)));
        asm("fma.rn.f32x2 %0, %1, %2, %0;" : "+l"(acc0) : "l"(w2), "l"(hh.x));
        asm("fma.rn.f32x2 %0, %1, %2, %0;" : "+l"(acc1) : "l"(w2), "l"(hh.y));
    }
    {
        float2 f0 = *(float2*)&acc0;
        float2 f1 = *(float2*)&acc1;
        Hfs[(4 * g + 0) * D + e] = fmaxf(f0.x, 0.f);
        Hfs[(4 * g + 1) * D + e] = fmaxf(f0.y, 0.f);
        Hfs[(4 * g + 2) * D + e] = fmaxf(f1.x, 0.f);
        Hfs[(4 * g + 3) * D + e] = fmaxf(f1.y, 0.f);
    }
    __syncthreads();

    // Reduction: warp w handles row w, 4 dot products over e
    {
        int r = warp;
        float s0 = 0.f, s1 = 0.f, s2 = 0.f, s3 = 0.f;
#pragma unroll
        for (int k = 0; k < 4; k++) {
            int ee = lane + 32 * k;
            float hv = Hfs[r * D + ee];
            float4 wc = *(const float4*)(Wcs + ee * 4);
            s0 = fmaf(hv, wc.x, s0);
            s1 = fmaf(hv, wc.y, s1);
            s2 = fmaf(hv, wc.z, s2);
            s3 = fmaf(hv, wc.w, s3);
        }
#pragma unroll
        for (int o = 16; o; o >>= 1) {
            s0 += __shfl_xor_sync(0xffffffffu, s0, o);
            s1 += __shfl_xor_sync(0xffffffffu, s1, o);
            s2 += __shfl_xor_sync(0xffffffffu, s2, o);
            s3 += __shfl_xor_sync(0xffffffffu, s3, o);
        }
        if (lane == 0)
            *(float4*)(g_r + (size_t)(grow0 + r) * 4) = make_float4(s0, s1, s2, s3);
    }
}

// ---------------------------------------------------------------------------
// Kernel C: logits[b,i,j,:] = li[b,i] + lj[b,j] + bc. Pure 8MB stream write.
// Grid: 256 blocks (8 rows each), 256 threads; one float4 store per (row,thread).
// ---------------------------------------------------------------------------
__global__ void expand_kernel(const float* __restrict__ bc,
                              float* __restrict__ out)
{
    __shared__ float2 lj_s[NN];
    const int tid = threadIdx.x;
    const int b   = blockIdx.x >> 6;
    const int i0  = (blockIdx.x & 63) * RPB;

    const float bc0 = bc[0], bc1 = bc[1];
#pragma unroll
    for (int k = 0; k < 2; k++) {
        int j = tid + k * 256;
        float2 lj = *(const float2*)(g_r + (size_t)(b * NN + j) * 4 + 2);
        lj_s[j] = make_float2(lj.x + bc0, lj.y + bc1);
    }
    __syncthreads();

    float4* out4 = (float4*)out;
    const float4 a = *(const float4*)(lj_s + 2 * tid);  // (ljx0,ljy0,ljx1,ljy1)
#pragma unroll
    for (int r = 0; r < RPB; r++) {
        int row = b * NN + i0 + r;
        float2 li = *(const float2*)(g_r + (size_t)row * 4);
        out4[(size_t)row * 256 + tid] =
            make_float4(li.x + a.x, li.y + a.y, li.x + a.z, li.y + a.w);
    }
}

// ---------------------------------------------------------------------------
extern "C" void kernel_launch(void* const* d_in, const int* in_sizes, int n_in,
                              void* d_out, int out_size)
{
    const int*   adj = (const int*)d_in[0];
    const int*   t   = (const int*)d_in[1];
    const float* TE  = (const float*)d_in[2];
    const float* nc  = (const float*)d_in[3];
    const float* EE  = (const float*)d_in[4];
    const float* W1  = (const float*)d_in[5];
    const float* b1  = (const float*)d_in[6];
    const float* W2  = (const float*)d_in[7];
    const float* b2  = (const float*)d_in[8];
    const float* Wc  = (const float*)d_in[9];
    const float* bc  = (const float*)d_in[10];
    float* out = (float*)d_out;

    (void)in_sizes; (void)n_in; (void)out_size;

    const int smem_b = SMEM_B_FLOATS * sizeof(float);
    cudaFuncSetAttribute(row_kernel, cudaFuncAttributeMaxDynamicSharedMemorySize, smem_b);

    setup_kernel<<<1, 128>>>(t, TE, nc, EE, W1, b1);
    row_kernel<<<256, 256, smem_b>>>(adj, W2, b2, Wc);
    expand_kernel<<<256, 256>>>(bc, out);
}

// round 3
// speedup vs baseline: 1.6976x; 1.6976x over previous
#include <cuda_runtime.h>
#include <cstdint>

#define D   128
#define NN  512
#define BB  4
#define RPB 8   // rows per block in row_kernel / expand_kernel

// Scratch (device globals — no allocation allowed)
__device__ float g_part[28 * D];     // 7 jobs x 4 f-chunks x 128 outputs
__device__ float g_r[BB * NN * 4];   // per row: li0, li1, lj0, lj1

// ---------------------------------------------------------------------------
// Kernel S: parallel fold of W1 against the 7 coefficient vectors.
//   job j=0: (E1-E0) . W1[0:128]      -> v1 contribution
//   job j=1:  E0     . W1[0:128]      -> base
//   job j=2:  nc     . W1[128:256]    -> base
//   job j=3..6: TE[t[b]] . W1[256:384]-> base (per batch)
// Grid 28 blocks = (j, f-chunk of 32), 128 threads (thread = output dim e).
// Coalesced loads, full unroll (MLP=32). Partials summed in row_kernel.
// ---------------------------------------------------------------------------
__global__ void setup_partial(const int* __restrict__ t,
                              const float* __restrict__ TE,
                              const float* __restrict__ nc,
                              const float* __restrict__ EE,
                              const float* __restrict__ W1)
{
    __shared__ float s_coef[32];
    const int j  = blockIdx.x >> 2;   // 0..6
    const int c  = blockIdx.x & 3;    // f-chunk
    const int e  = threadIdx.x;       // 0..127
    const int f0 = c * 32;

    if (e < 32) {
        int f = f0 + e;
        float v;
        if (j == 0)      v = EE[D + f] - EE[f];
        else if (j == 1) v = EE[f];
        else if (j == 2) v = nc[f];
        else             v = TE[(size_t)t[j - 3] * D + f];
        s_coef[e] = v;
    }
    __syncthreads();

    const int blk = (j <= 1) ? 0 : (j == 2 ? 1 : 2);
    const float* W = W1 + ((size_t)blk * D + f0) * D + e;
    float acc = 0.f;
#pragma unroll
    for (int f = 0; f < 32; f++)
        acc = fmaf(s_coef[f], W[(size_t)f * D], acc);
    g_part[blockIdx.x * D + e] = acc;
}

// ---------------------------------------------------------------------------
// Kernel B: per row i — p = mean(adj[b,i,:]); h = relu(p*v1 + base[b]);
// Hf = relu(h @ W2 + b2); (li, lj) = Hf @ Wc halves. Stores 4 floats/row.
// Inline finalize of g_part -> (v1, base) per thread (L2-hot, 16 loads).
// Grid: 256 blocks (64 per batch, 8 rows each), 256 threads.
// Dynamic smem: W2 (64KB) + h (4KB) + Hf (4KB) + Wc (2KB) + p (32B)
// ---------------------------------------------------------------------------
#define SMEM_B_FLOATS (16384 + 1024 + 1024 + 512 + 8)

__global__ void row_kernel(const int* __restrict__ adj,
                           const float* __restrict__ W2,
                           const float* __restrict__ b1,
                           const float* __restrict__ b2,
                           const float* __restrict__ Wc)
{
    extern __shared__ float smem[];
    float* W2s = smem;                       // [d*128 + e]
    float* h_s = smem + 16384;               // [d*8 + r]
    float* Hfs = smem + 16384 + 1024;        // [r*128 + e]
    float* Wcs = smem + 16384 + 2048;        // [e*4 + c]  (li0,li1,lj0,lj1 weights)
    float* p_s = smem + 16384 + 2048 + 512;  // [8]

    const int tid  = threadIdx.x;
    const int b    = blockIdx.x >> 6;
    const int i0   = (blockIdx.x & 63) * RPB;
    const int grow0 = b * NN + i0;

    const int e    = tid & 127;
    const int g    = tid >> 7;       // 0/1: which 4-row group
    const int warp = tid >> 5;       // 0..7
    const int lane = tid & 31;

    // Load W2 into shared (coalesced float4 copy)
    {
        const float4* W2_4 = (const float4*)W2;
        float4* W2s_4 = (float4*)W2s;
#pragma unroll
        for (int k = 0; k < 16; k++) W2s_4[tid + k * 256] = W2_4[tid + k * 256];
    }

    // Finalize setup partials: v1[e], base[b][e] (16 independent L2 loads)
    float v1e   = 0.f;
    float basee = b1[e];
#pragma unroll
    for (int c = 0; c < 4; c++) {
        v1e   += g_part[(0 * 4 + c) * D + e];
        basee += g_part[(1 * 4 + c) * D + e]
               + g_part[(2 * 4 + c) * D + e]
               + g_part[((3 + b) * 4 + c) * D + e];
    }
    const float b2e = b2[e];
    if (g == 0) {
        float4 wc = make_float4(Wc[e * 2 + 0], Wc[e * 2 + 1],
                                Wc[(D + e) * 2 + 0], Wc[(D + e) * 2 + 1]);
        *(float4*)(Wcs + e * 4) = wc;
    }

    // p: warp w reduces row w (512 ints = 128 int4)
    {
        const int4* a4 = (const int4*)adj + (size_t)grow0 * (NN / 4);
        int s = 0;
#pragma unroll
        for (int k = 0; k < 4; k++) {
            int4 v = a4[warp * 128 + k * 32 + lane];
            s += v.x + v.y + v.z + v.w;
        }
#pragma unroll
        for (int o = 16; o; o >>= 1) s += __shfl_xor_sync(0xffffffffu, s, o);
        if (lane == 0) p_s[warp] = (float)s * (1.0f / 512.0f);
    }
    __syncthreads();

    // h for this thread's 4 rows at element e
    {
        float4 pr = *(const float4*)(p_s + 4 * g);
        float h0 = fmaxf(fmaf(pr.x, v1e, basee), 0.f);
        float h1 = fmaxf(fmaf(pr.y, v1e, basee), 0.f);
        float h2 = fmaxf(fmaf(pr.z, v1e, basee), 0.f);
        float h3 = fmaxf(fmaf(pr.w, v1e, basee), 0.f);
        *(float4*)(h_s + e * 8 + 4 * g) = make_float4(h0, h1, h2, h3);
    }
    __syncthreads();

    // Matvec: Hf[r][e] = relu(sum_d h[r][d] * W2[d][e] + b2[e]), 4 rows via f32x2
    unsigned long long acc0, acc1;
    {
        unsigned int ub = __float_as_uint(b2e);
        asm("mov.b64 %0, {%1, %1};" : "=l"(acc0) : "r"(ub));
        acc1 = acc0;
    }
#pragma unroll 8
    for (int d = 0; d < D; d++) {
        float w = W2s[d * D + e];
        ulonglong2 hh = *(const ulonglong2*)(h_s + d * 8 + 4 * g);
        unsigned long long w2;
        asm("mov.b64 %0, {%1, %1};" : "=l"(w2) : "r"(__float_as_uint(w)));
        asm("fma.rn.f32x2 %0, %1, %2, %0;" : "+l"(acc0) : "l"(w2), "l"(hh.x));
        asm("fma.rn.f32x2 %0, %1, %2, %0;" : "+l"(acc1) : "l"(w2), "l"(hh.y));
    }
    {
        float2 f0 = *(float2*)&acc0;
        float2 f1 = *(float2*)&acc1;
        Hfs[(4 * g + 0) * D + e] = fmaxf(f0.x, 0.f);
        Hfs[(4 * g + 1) * D + e] = fmaxf(f0.y, 0.f);
        Hfs[(4 * g + 2) * D + e] = fmaxf(f1.x, 0.f);
        Hfs[(4 * g + 3) * D + e] = fmaxf(f1.y, 0.f);
    }
    __syncthreads();

    // Reduction: warp w handles row w, 4 dot products over e
    {
        int r = warp;
        float s0 = 0.f, s1 = 0.f, s2 = 0.f, s3 = 0.f;
#pragma unroll
        for (int k = 0; k < 4; k++) {
            int ee = lane + 32 * k;
            float hv = Hfs[r * D + ee];
            float4 wc = *(const float4*)(Wcs + ee * 4);
            s0 = fmaf(hv, wc.x, s0);
            s1 = fmaf(hv, wc.y, s1);
            s2 = fmaf(hv, wc.z, s2);
            s3 = fmaf(hv, wc.w, s3);
        }
#pragma unroll
        for (int o = 16; o; o >>= 1) {
            s0 += __shfl_xor_sync(0xffffffffu, s0, o);
            s1 += __shfl_xor_sync(0xffffffffu, s1, o);
            s2 += __shfl_xor_sync(0xffffffffu, s2, o);
            s3 += __shfl_xor_sync(0xffffffffu, s3, o);
        }
        if (lane == 0)
            *(float4*)(g_r + (size_t)(grow0 + r) * 4) = make_float4(s0, s1, s2, s3);
    }
}

// ---------------------------------------------------------------------------
// Kernel C: logits[b,i,j,:] = li[b,i] + lj[b,j] + bc. Pure 8MB stream write.
// Grid: 256 blocks (8 rows each), 256 threads; one float4 store per (row,thread).
// ---------------------------------------------------------------------------
__global__ void expand_kernel(const float* __restrict__ bc,
                              float* __restrict__ out)
{
    __shared__ float2 lj_s[NN];
    const int tid = threadIdx.x;
    const int b   = blockIdx.x >> 6;
    const int i0  = (blockIdx.x & 63) * RPB;

    const float bc0 = bc[0], bc1 = bc[1];
#pragma unroll
    for (int k = 0; k < 2; k++) {
        int j = tid + k * 256;
        float2 lj = *(const float2*)(g_r + (size_t)(b * NN + j) * 4 + 2);
        lj_s[j] = make_float2(lj.x + bc0, lj.y + bc1);
    }
    __syncthreads();

    float4* out4 = (float4*)out;
    const float4 a = *(const float4*)(lj_s + 2 * tid);  // (ljx0,ljy0,ljx1,ljy1)
#pragma unroll
    for (int r = 0; r < RPB; r++) {
        int row = b * NN + i0 + r;
        float2 li = *(const float2*)(g_r + (size_t)row * 4);
        out4[(size_t)row * 256 + tid] =
            make_float4(li.x + a.x, li.y + a.y, li.x + a.z, li.y + a.w);
    }
}

// ---------------------------------------------------------------------------
extern "C" void kernel_launch(void* const* d_in, const int* in_sizes, int n_in,
                              void* d_out, int out_size)
{
    const int*   adj = (const int*)d_in[0];
    const int*   t   = (const int*)d_in[1];
    const float* TE  = (const float*)d_in[2];
    const float* nc  = (const float*)d_in[3];
    const float* EE  = (const float*)d_in[4];
    const float* W1  = (const float*)d_in[5];
    const float* b1  = (const float*)d_in[6];
    const float* W2  = (const float*)d_in[7];
    const float* b2  = (const float*)d_in[8];
    const float* Wc  = (const float*)d_in[9];
    const float* bc  = (const float*)d_in[10];
    float* out = (float*)d_out;

    (void)in_sizes; (void)n_in; (void)out_size;

    const int smem_b = SMEM_B_FLOATS * sizeof(float);
    cudaFuncSetAttribute(row_kernel, cudaFuncAttributeMaxDynamicSharedMemorySize, smem_b);

    setup_partial<<<28, 128>>>(t, TE, nc, EE, W1);
    row_kernel<<<256, 256, smem_b>>>(adj, W2, b1, b2, Wc);
    expand_kernel<<<256, 256>>>(bc, out);
}